// round 1
// baseline (speedup 1.0000x reference)
#include <cuda_runtime.h>

#define B_ 16
#define L_ 576
#define H_ 12
#define D_ 64
#define M_ 8
#define NUM_STAB 1e-3f
#define RATIO 0.35355339059327373f   /* 1/sqrt(M) */

// -------- scratch (device globals: no allocation allowed) --------
__device__ float g_qp[B_ * H_ * L_ * M_];   // q' features, [B,H,L,M]
__device__ float g_kp[B_ * H_ * L_ * M_];   // k' features, [B,H,L,M]
__device__ float g_cmask[H_ * L_];          // column sums of mask over i
__device__ float g_ks[B_ * H_ * M_];        // ks_sum[b,h,m]

// -------- packed f32x2 helpers (sm_100+) --------
__device__ __forceinline__ unsigned long long pack2(float x, float y) {
    unsigned long long r;
    asm("mov.b64 %0, {%1, %2};" : "=l"(r) : "f"(x), "f"(y));
    return r;
}
__device__ __forceinline__ void ffma2(unsigned long long& d,
                                      unsigned long long a,
                                      unsigned long long b) {
    asm("fma.rn.f32x2 %0, %1, %2, %0;" : "+l"(d) : "l"(a), "l"(b));
}
__device__ __forceinline__ float2 unpack2(unsigned long long v) {
    float2 r;
    asm("mov.b64 {%0, %1}, %2;" : "=f"(r.x), "=f"(r.y) : "l"(v));
    return r;
}

// ============================================================
// Kernel 1: ReLU random features.  blockIdx.y: 0 -> query, 1 -> key.
// out layout [B,H,L,M] for contiguous per-(b,h) access later.
// ============================================================
__global__ void feat_kernel(const float* __restrict__ q,
                            const float* __restrict__ k,
                            const float* __restrict__ proj) {
    __shared__ float ps[M_ * D_];
    int tid = threadIdx.x;
    for (int i = tid; i < M_ * D_; i += blockDim.x) ps[i] = proj[i];
    __syncthreads();

    const float* x  = blockIdx.y ? k : q;
    float* out      = blockIdx.y ? g_kp : g_qp;

    int t = blockIdx.x * blockDim.x + tid;
    if (t >= B_ * L_ * H_ * M_) return;
    int row = t >> 3;       // (b*L + l)*H + h
    int m   = t & 7;

    const float4* xr = (const float4*)(x + (size_t)row * D_);
    const float4* pr = (const float4*)(ps + m * D_);
    float acc = 0.0f;
#pragma unroll
    for (int i = 0; i < D_ / 4; i++) {
        float4 a = xr[i];
        float4 b = pr[i];
        acc += a.x * b.x + a.y * b.y + a.z * b.z + a.w * b.w;
    }
    int b = row / (L_ * H_);
    int l = (row / H_) % L_;
    int h = row % H_;
    out[(((size_t)(b * H_ + h) * L_ + l) << 3) + m] =
        fmaxf(RATIO * acc, 0.0f) + NUM_STAB;
}

// ============================================================
// Kernel 2: cmask[h,j] = sum_i mask[h,i,j]
// ============================================================
__global__ void cmask_kernel(const float* __restrict__ mask) {
    int h = blockIdx.y;
    int j = blockIdx.x * blockDim.x + threadIdx.x;
    if (j >= L_) return;
    const float* mp = mask + (size_t)h * L_ * L_ + j;
    float s = 0.0f;
#pragma unroll 8
    for (int i = 0; i < L_; i++) s += mp[(size_t)i * L_];
    g_cmask[h * L_ + j] = s;
}

// ============================================================
// Kernel 3: ks_sum[b,h,m] = sum_j cmask[h,j] * k'[b,h,j,m]
// one 64-thread block per (b,h)
// ============================================================
__global__ void ks_kernel() {
    int bh = blockIdx.x;
    int h  = bh % H_;
    int tid = threadIdx.x;
    __shared__ float red[64][8];

    float acc[8];
#pragma unroll
    for (int m = 0; m < 8; m++) acc[m] = 0.0f;

    for (int j = tid; j < L_; j += 64) {
        float c = g_cmask[h * L_ + j];
        const float4* kr = (const float4*)(g_kp + ((size_t)bh * L_ + j) * 8);
        float4 a = kr[0], bb = kr[1];
        acc[0] += c * a.x;  acc[1] += c * a.y;
        acc[2] += c * a.z;  acc[3] += c * a.w;
        acc[4] += c * bb.x; acc[5] += c * bb.y;
        acc[6] += c * bb.z; acc[7] += c * bb.w;
    }
#pragma unroll
    for (int m = 0; m < 8; m++) red[tid][m] = acc[m];
    __syncthreads();
    if (tid < 8) {
        float s = 0.0f;
        for (int i = 0; i < 64; i++) s += red[i][tid];
        g_ks[bh * 8 + tid] = s;
    }
}

// ============================================================
// Kernel 4: fused masked linear attention.
// grid (L/64, H, B), block 64.  Each CTA: 64 output rows x 64 cols.
// Per j-tile: S = Q'K'^T (depth 8), A = mask .* S -> smem (transposed),
// then O += A @ V (depth 64) with f32x2 packed FMA, 8x8 per thread.
// Epilogue: divide by normalizer q'.ks_sum, store.
// ============================================================
__global__ void __launch_bounds__(64)
attn_kernel(const float* __restrict__ v,
            const float* __restrict__ mask,
            float* __restrict__ out) {
    const int it = blockIdx.x, h = blockIdx.y, b = blockIdx.z;
    const int i0 = it * 64;
    const int bh = b * H_ + h;
    const int tid = threadIdx.x;

    __shared__ float Qs[64 * 8];
    __shared__ float Ks[64 * 8];
    __shared__ float As[64][68];   // As[j][i]  (A transposed, padded)
    __shared__ float Vs[64][68];   // Vs[j][d]
    __shared__ float KSs[8];

    // load Q' tile (contiguous in [B,H,L,M]) and ks_sum
    {
        const float4* src = (const float4*)(g_qp + ((size_t)bh * L_ + i0) * 8);
        float4* dst = (float4*)Qs;
        dst[tid] = src[tid];
        dst[tid + 64] = src[tid + 64];
    }
    if (tid < 8) KSs[tid] = g_ks[bh * 8 + tid];

    const int ty = tid >> 3, tx = tid & 7;
    const int r0 = ty * 8, c0 = tx * 8;

    unsigned long long acc[8][4];
#pragma unroll
    for (int r = 0; r < 8; r++)
#pragma unroll
        for (int c = 0; c < 4; c++) acc[r][c] = 0ULL;

    const float* maskh = mask + (size_t)h * L_ * L_;
    const float* vbase = v + (((size_t)b * L_) * H_ + h) * D_;

    for (int jt = 0; jt < L_ / 64; jt++) {
        const int j0 = jt * 64;
        __syncthreads();   // previous AV reads done before overwrite

        // ---- load K' tile (contiguous) ----
        {
            const float4* src = (const float4*)(g_kp + ((size_t)bh * L_ + j0) * 8);
            float4* dst = (float4*)Ks;
            dst[tid] = src[tid];
            dst[tid + 64] = src[tid + 64];
        }
        // ---- load V tile: 64 rows x 64 floats, coalesced ----
#pragma unroll
        for (int rep = 0; rep < 16; rep++) {
            int idx = rep * 64 + tid;
            int r = idx >> 4, d4 = idx & 15;
            float4 val = __ldg((const float4*)(vbase + (size_t)(j0 + r) * (H_ * D_) + d4 * 4));
            *(float4*)&Vs[r][d4 * 4] = val;
        }
        __syncthreads();

        // ---- S phase: this thread owns column j = j0 + tid ----
        {
            float kr[8];
            {
                float4 ka = *(const float4*)(Ks + tid * 8);
                float4 kb = *(const float4*)(Ks + tid * 8 + 4);
                kr[0] = ka.x; kr[1] = ka.y; kr[2] = ka.z; kr[3] = ka.w;
                kr[4] = kb.x; kr[5] = kb.y; kr[6] = kb.z; kr[7] = kb.w;
            }
            const float* mcol = maskh + (size_t)i0 * L_ + j0 + tid;
#pragma unroll 4
            for (int i4 = 0; i4 < 16; i4++) {
                float mv0 = __ldg(mcol + (size_t)(i4 * 4 + 0) * L_);
                float mv1 = __ldg(mcol + (size_t)(i4 * 4 + 1) * L_);
                float mv2 = __ldg(mcol + (size_t)(i4 * 4 + 2) * L_);
                float mv3 = __ldg(mcol + (size_t)(i4 * 4 + 3) * L_);
                float4 sb;
                float* sp = &sb.x;
                float mvv[4] = {mv0, mv1, mv2, mv3};
#pragma unroll
                for (int ii = 0; ii < 4; ii++) {
                    int i = i4 * 4 + ii;
                    float4 qa = *(const float4*)(Qs + i * 8);
                    float4 qb = *(const float4*)(Qs + i * 8 + 4);
                    float s = qa.x * kr[0] + qa.y * kr[1] + qa.z * kr[2] + qa.w * kr[3]
                            + qb.x * kr[4] + qb.y * kr[5] + qb.z * kr[6] + qb.w * kr[7];
                    sp[ii] = s * mvv[ii];
                }
                *(float4*)&As[tid][i4 * 4] = sb;
            }
        }
        __syncthreads();

        // ---- AV phase: O[r0..r0+7][c0..c0+7] += A[r][k] * V[k][c] ----
#pragma unroll 8
        for (int k = 0; k < 64; k++) {
            float4 alo = *(const float4*)(&As[k][r0]);
            float4 ahi = *(const float4*)(&As[k][r0 + 4]);
            // V pairs load directly as packed f32x2 (adjacent floats)
            ulonglong2 v01 = *(const ulonglong2*)(&Vs[k][c0]);
            ulonglong2 v23 = *(const ulonglong2*)(&Vs[k][c0 + 4]);
            unsigned long long vv[4] = {v01.x, v01.y, v23.x, v23.y};
            float ar[8] = {alo.x, alo.y, alo.z, alo.w, ahi.x, ahi.y, ahi.z, ahi.w};
#pragma unroll
            for (int rr = 0; rr < 8; rr++) {
                unsigned long long a2 = pack2(ar[rr], ar[rr]);
                ffma2(acc[rr][0], a2, vv[0]);
                ffma2(acc[rr][1], a2, vv[1]);
                ffma2(acc[rr][2], a2, vv[2]);
                ffma2(acc[rr][3], a2, vv[3]);
            }
        }
    }

    // ---- epilogue: normalizer + store ----
    float* obase = out + (((size_t)b * L_ + i0) * H_ + h) * D_;
#pragma unroll
    for (int rr = 0; rr < 8; rr++) {
        int i = r0 + rr;
        float norm = 0.0f;
#pragma unroll
        for (int m = 0; m < 8; m++) norm += Qs[i * 8 + m] * KSs[m];
        float rn = 1.0f / norm;
        float2 p0 = unpack2(acc[rr][0]);
        float2 p1 = unpack2(acc[rr][1]);
        float2 p2 = unpack2(acc[rr][2]);
        float2 p3 = unpack2(acc[rr][3]);
        float4 w0 = make_float4(p0.x * rn, p0.y * rn, p1.x * rn, p1.y * rn);
        float4 w1 = make_float4(p2.x * rn, p2.y * rn, p3.x * rn, p3.y * rn);
        float* op = obase + (size_t)i * (H_ * D_) + c0;
        *(float4*)op = w0;
        *(float4*)(op + 4) = w1;
    }
}

// ============================================================
extern "C" void kernel_launch(void* const* d_in, const int* in_sizes, int n_in,
                              void* d_out, int out_size) {
    const float* q    = (const float*)d_in[0];
    const float* k    = (const float*)d_in[1];
    const float* v    = (const float*)d_in[2];
    const float* proj = (const float*)d_in[3];
    const float* mask = (const float*)d_in[4];
    float* out = (float*)d_out;

    // 1) ReLU features for q and k
    {
        int total = B_ * L_ * H_ * M_;
        dim3 grid((total + 255) / 256, 2);
        feat_kernel<<<grid, 256>>>(q, k, proj);
    }
    // 2) mask column sums
    {
        dim3 grid((L_ + 255) / 256, H_);
        cmask_kernel<<<grid, 256>>>(mask);
    }
    // 3) ks_sum
    ks_kernel<<<B_ * H_, 64>>>();
    // 4) fused masked linear attention
    {
        dim3 grid(L_ / 64, H_, B_);
        attn_kernel<<<grid, 64>>>(v, mask, out);
    }
}